// round 15
// baseline (speedup 1.0000x reference)
#include <cuda_runtime.h>
#include <math.h>

#define NB    8
#define NA    3
#define NH    160
#define NW    160
#define NCLS  80
#define NLOC  (NA*NH*NW)          // 76800 per batch
#define NGT   32
#define STRIDE_F 8.0f

#define TILE   128                 // locations per block
#define NBLK   (NB*NLOC/TILE)      // 4800
#define BLK_PER_B (NLOC/TILE)      // 600
#define ROWF4  21                  // float4 per location row (20 + 1 pad)

#define OFF_PBBOX  0
#define OFF_CLSIDX (NB*NLOC*4)
#define OFF_SCORE  (NB*NLOC*4 + NB*NLOC)
#define OFF_LOSS   (NB*NLOC*4 + 2*NB*NLOC)

__device__ double       g_loss_acc;
__device__ unsigned int g_done_count;

__constant__ float c_anchors[9][2] = {
    {10.f,13.f},{16.f,30.f},{33.f,23.f},{30.f,61.f},{62.f,45.f},
    {59.f,119.f},{116.f,90.f},{156.f,198.f},{373.f,326.f}};

__device__ __forceinline__ float sigmoidf_(float x) {
    return __fdividef(1.0f, 1.0f + __expf(-x));
}
__device__ __forceinline__ float bce_(float x, float t) {
    return fmaxf(x, 0.0f) - x * t + log1pf(__expf(-fabsf(x)));
}

// ---------------------------------------------------------------------------
// Round-8 structure (TILE=128, 2 thr/loc, warp-private cp.async, pad-21
// conflict-free smem) with pair-redundancy removed:
//  - only h==0 lanes load t_bbox/conf and run the decode chain;
//    IoU inputs (ax1,ax2,ay1,ay2,areaA) broadcast via 5 shfl from lane&15.
//  - streaming stores (__stcs) for all outputs.
// ---------------------------------------------------------------------------
__global__ __launch_bounds__(256) void main_kernel(
    const float* __restrict__ t_bbox,
    const float* __restrict__ conf,
    const float* __restrict__ cls,
    const float* __restrict__ gt,
    const int*   __restrict__ gt_cls,
    const unsigned char* __restrict__ gt_mask,
    float* __restrict__ out)
{
    __shared__ float4 s_cls[TILE * ROWF4];       // 43008 B
    __shared__ float4 s_gtc[NGT + 2];            // corners, pad g + g/16
    __shared__ float  s_areaB[NGT];
    __shared__ float  s_warp[8];

    const int tid    = threadIdx.x;
    const int w      = tid >> 5;
    const int lane   = tid & 31;
    const int blkmod = blockIdx.x % BLK_PER_B;
    const int b      = blockIdx.x / BLK_PER_B;
    const int nbase  = blkmod * TILE;

    // --- P1: warp-owned cp.async (warp w -> locs [w*16, w*16+16)) ---
    {
        const float4* src = reinterpret_cast<const float4*>(cls)
                          + (b * NLOC + nbase) * 20;
        unsigned sbase = (unsigned)__cvta_generic_to_shared(s_cls);
        #pragma unroll
        for (int k = 0; k < 10; k++) {
            int fi = w * 320 + k * 32 + lane;
            unsigned dst = sbase + (unsigned)(fi + fi / 20) * 16u;
            asm volatile("cp.async.cg.shared.global [%0], [%1], 16;"
                         :: "r"(dst), "l"(src + fi) : "memory");
        }
        asm volatile("cp.async.commit_group;" ::: "memory");
    }

    // --- GT staging: every warp writes identical values (benign race) ---
    {
        float4 g = reinterpret_cast<const float4*>(gt)[b * NGT + lane];
        int valid = gt_mask[b * NGT + lane];
        int si = lane + (lane >> 4);
        if (valid) {
            s_gtc[si] = make_float4(g.x - g.z * 0.5f, g.y - g.w * 0.5f,
                                    g.x + g.z * 0.5f, g.y + g.w * 0.5f);
            s_areaB[lane] = g.z * g.w;
        } else {
            s_gtc[si] = make_float4(-3e8f, -3e8f, -3e8f, -3e8f);
            s_areaB[lane] = 0.0f;
        }
    }

    // pair mapping: h = lane>>4, loc = w*16 + (lane&15)
    const int loc  = (w << 4) + (lane & 15);
    const int h    = lane >> 4;
    const int n    = nbase + loc;
    const int gloc = b * NLOC + n;
    const unsigned FULL = 0xffffffffu;

    // --- h==0 lanes only: prefetch t_bbox/conf while cp.async drains ---
    float4 t = make_float4(0.f, 0.f, 0.f, 0.f);
    float conf_logit = 0.0f;
    if (h == 0) {
        t = reinterpret_cast<const float4*>(t_bbox)[gloc];
        conf_logit = conf[gloc];
    }

    asm volatile("cp.async.wait_group 0;" ::: "memory");
    __syncwarp();

    // --- P2: class max/argmax (cg = 2k + h, pad-21 conflict-free) ---
    const int base = loc * ROWF4;
    float gm = -1e30f; int gcg = h;
    {
        #pragma unroll
        for (int k = 0; k < 10; k++) {
            int cg = 2 * k + h;
            float4 v = s_cls[base + cg];
            float m = fmaxf(fmaxf(v.x, v.y), fmaxf(v.z, v.w));
            if (m > gm) { gm = m; gcg = cg; }
        }
    }
    float mv = gm; int mi;
    {
        float4 v = s_cls[base + gcg];
        int r = (v.z == gm) ? 2 : 3;
        if (v.y == gm) r = 1;
        if (v.x == gm) r = 0;
        mi = gcg * 4 + r;
    }
    {
        float ov = __shfl_xor_sync(FULL, mv, 16);
        int   oi = __shfl_xor_sync(FULL, mi, 16);
        if (ov > mv || (ov == mv && oi < mi)) { mv = ov; mi = oi; }
    }

    // --- P3: decode on h==0 only, broadcast IoU inputs to h==1 ---
    float px = 0.f, py = 0.f, pw = 0.f, ph = 0.f;
    float ax1 = 0.f, ax2 = 0.f, ay1 = 0.f, ay2 = 0.f, areaA = 0.f;
    if (h == 0) {
        const int a   = blkmod / 200;                   // block-uniform
        const int rem = (blkmod % 200) * TILE + loc;    // n % 25600
        const int j   = rem / NW;
        const int i   = rem - j * NW;
        float sx = sigmoidf_(t.x), sy = sigmoidf_(t.y);
        float sw = sigmoidf_(t.z), sh = sigmoidf_(t.w);
        px = (sx * 2.0f - 0.5f + (float)i) * STRIDE_F;
        py = (sy * 2.0f - 0.5f + (float)j) * STRIDE_F;
        float tw = sw * 2.0f, th = sh * 2.0f;
        pw = tw * tw * c_anchors[a][0];
        ph = th * th * c_anchors[a][1];
        ax1 = px - pw * 0.5f; ax2 = px + pw * 0.5f;
        ay1 = py - ph * 0.5f; ay2 = py + ph * 0.5f;
        areaA = pw * ph;
    }
    {
        int srcl = lane & 15;
        ax1   = __shfl_sync(FULL, ax1,   srcl);
        ax2   = __shfl_sync(FULL, ax2,   srcl);
        ay1   = __shfl_sync(FULL, ay1,   srcl);
        ay2   = __shfl_sync(FULL, ay2,   srcl);
        areaA = __shfl_sync(FULL, areaA, srcl);
    }

    // --- IoU vs 16 GTs per half ---
    float iou = 0.0f;
    #pragma unroll
    for (int k = 0; k < 16; k++) {
        int g = h * 16 + k;
        float4 c = s_gtc[g + (g >> 4)];
        float iw = fmaxf(fminf(ax2, c.z) - fmaxf(ax1, c.x), 0.0f);
        float ih = fmaxf(fminf(ay2, c.w) - fmaxf(ay1, c.y), 0.0f);
        float inter = iw * ih;
        float uni = areaA + s_areaB[g] - inter;
        iou = fmaxf(iou, __fdividef(inter, uni + 1e-16f));
    }
    iou = fmaxf(iou, __shfl_xor_sync(FULL, iou, 16));

    // --- h==0 lanes: streaming outputs + conf bce ---
    float lsum = 0.0f;
    if (h == 0) {
        lsum = bce_(conf_logit, iou);
        __stcs(reinterpret_cast<float4*>(out + OFF_PBBOX) + gloc,
               make_float4(px, py, pw, ph));
        __stcs(out + OFF_CLSIDX + gloc, (float)mi);
        __stcs(out + OFF_SCORE  + gloc, sigmoidf_(conf_logit) * sigmoidf_(mv));
    }

    // --- block 0 additionally: per-GT losses, one GT per thread ---
    if (blockIdx.x == 0) {
        int gb = tid / NGT;
        int gg = tid % NGT;
        if (gt_mask[gb * NGT + gg]) {
            float4 gbx = reinterpret_cast<const float4*>(gt)[gb * NGT + gg];
            float gw = gbx.z, gh = gbx.w;
            int best = 0; float bestr = -1.0f;
            #pragma unroll
            for (int aa = 0; aa < 9; aa++) {
                float aw = c_anchors[aa][0], ah = c_anchors[aa][1];
                float inter = fminf(gw, aw) * fminf(gh, ah);
                float uni = gw * gh + aw * ah - inter;
                float r = inter / (uni + 1e-16f);
                if (r > bestr) { bestr = r; best = aa; }
            }
            if (best < NA) {
                int ta = best;
                float cxs = gbx.x * (1.0f / STRIDE_F);
                float cys = gbx.y * (1.0f / STRIDE_F);
                int ti = min(max((int)cxs, 0), NW - 1);
                int tj = min(max((int)cys, 0), NH - 1);
                int cell = ((gb * NA + ta) * NH + tj) * NW + ti;
                float4 tb = reinterpret_cast<const float4*>(t_bbox)[cell];
                float tgx = (fmodf(cxs, 1.0f) + 0.5f) * 0.5f;
                float tgy = (fmodf(cys, 1.0f) + 0.5f) * 0.5f;
                float tgw = sqrtf(gw / c_anchors[ta][0]) * 0.5f;
                float tgh = sqrtf(gh / c_anchors[ta][1]) * 0.5f;
                lsum += bce_(tb.x, tgx) + bce_(tb.y, tgy);
                lsum += bce_(tb.z, tgw) + bce_(tb.w, tgh);
                const float* cl = cls + cell * NCLS;
                int tc = gt_cls[gb * NGT + gg];
                float lcls = 0.0f;
                #pragma unroll 8
                for (int c = 0; c < NCLS; c++)
                    lcls += bce_(cl[c], (c == tc) ? 1.0f : 0.0f);
                lsum += lcls * (1.0f / NCLS);
            }
        }
    }

    // --- block reduction -> global double accumulator (single barrier) ---
    #pragma unroll
    for (int off = 16; off; off >>= 1)
        lsum += __shfl_down_sync(FULL, lsum, off);
    if (lane == 0) s_warp[w] = lsum;
    __syncthreads();
    if (tid == 0) {
        float s = 0.0f;
        #pragma unroll
        for (int k = 0; k < 8; k++) s += s_warp[k];
        atomicAdd(&g_loss_acc, (double)s);
        __threadfence();
        unsigned int done = atomicAdd(&g_done_count, 1u);
        if (done == NBLK - 1) {
            double total = atomicAdd(&g_loss_acc, 0.0);
            out[OFF_LOSS] = (float)(total * (1.0 / (double)NB));
            g_loss_acc   = 0.0;
            g_done_count = 0u;
        }
    }
}

extern "C" void kernel_launch(void* const* d_in, const int* in_sizes, int n_in,
                              void* d_out, int out_size)
{
    const float* t_bbox = (const float*)d_in[0];
    const float* conf   = (const float*)d_in[1];
    const float* cls    = (const float*)d_in[2];
    const float* gt     = (const float*)d_in[3];
    const int*   gtc    = (const int*)d_in[4];
    const unsigned char* msk = (const unsigned char*)d_in[5];
    float* out = (float*)d_out;

    main_kernel<<<NBLK, 256>>>(t_bbox, conf, cls, gt, gtc, msk, out);
}

// round 16
// speedup vs baseline: 1.4235x; 1.4235x over previous
#include <cuda_runtime.h>
#include <math.h>

#define NB    8
#define NA    3
#define NH    160
#define NW    160
#define NCLS  80
#define NLOC  (NA*NH*NW)          // 76800 per batch
#define NGT   32
#define STRIDE_F 8.0f

#define TILE   128                 // locations per block
#define NBLK   (NB*NLOC/TILE)      // 4800
#define BLK_PER_B (NLOC/TILE)      // 600
#define ROWF4  21                  // float4 per location row (20 + 1 pad)

#define OFF_PBBOX  0
#define OFF_CLSIDX (NB*NLOC*4)
#define OFF_SCORE  (NB*NLOC*4 + NB*NLOC)
#define OFF_LOSS   (NB*NLOC*4 + 2*NB*NLOC)

__device__ double       g_loss_acc;
__device__ unsigned int g_done_count;

__constant__ float c_anchors[9][2] = {
    {10.f,13.f},{16.f,30.f},{33.f,23.f},{30.f,61.f},{62.f,45.f},
    {59.f,119.f},{116.f,90.f},{156.f,198.f},{373.f,326.f}};

__device__ __forceinline__ float sigmoidf_(float x) {
    return __fdividef(1.0f, 1.0f + __expf(-x));
}
__device__ __forceinline__ float bce_(float x, float t) {
    return fmaxf(x, 0.0f) - x * t + log1pf(__expf(-fabsf(x)));
}

// ---------------------------------------------------------------------------
// Round-8 structure (TILE=128, 2 thr/loc, warp-private cp.async, pad-21)
// with the compute REORDERED for latency overlap:
//   issue cp.async -> GT staging -> decode + IoU (cls-independent, ~120
//   instrs) -> wait_group -> argmax -> outputs.
// The decode/IoU work now hides the smem-fill latency instead of following
// it. Redundant decode on both halves (rounds 9/11/15 showed redundancy
// beats shuffles here). __stcs on output streams.
// ---------------------------------------------------------------------------
__global__ __launch_bounds__(256) void main_kernel(
    const float* __restrict__ t_bbox,
    const float* __restrict__ conf,
    const float* __restrict__ cls,
    const float* __restrict__ gt,
    const int*   __restrict__ gt_cls,
    const unsigned char* __restrict__ gt_mask,
    float* __restrict__ out)
{
    __shared__ float4 s_cls[TILE * ROWF4];       // 43008 B
    __shared__ float4 s_gtc[NGT + 2];            // corners, pad g + g/16
    __shared__ float  s_areaB[NGT];
    __shared__ float  s_warp[8];

    const int tid    = threadIdx.x;
    const int w      = tid >> 5;
    const int lane   = tid & 31;
    const int blkmod = blockIdx.x % BLK_PER_B;
    const int b      = blockIdx.x / BLK_PER_B;
    const int nbase  = blkmod * TILE;

    // --- P1: warp-owned cp.async (warp w -> locs [w*16, w*16+16)) ---
    {
        const float4* src = reinterpret_cast<const float4*>(cls)
                          + (b * NLOC + nbase) * 20;
        unsigned sbase = (unsigned)__cvta_generic_to_shared(s_cls);
        #pragma unroll
        for (int k = 0; k < 10; k++) {
            int fi = w * 320 + k * 32 + lane;
            unsigned dst = sbase + (unsigned)(fi + fi / 20) * 16u;
            asm volatile("cp.async.cg.shared.global [%0], [%1], 16;"
                         :: "r"(dst), "l"(src + fi) : "memory");
        }
        asm volatile("cp.async.commit_group;" ::: "memory");
    }

    // --- GT staging: every warp writes identical values (benign race) ---
    {
        float4 g = reinterpret_cast<const float4*>(gt)[b * NGT + lane];
        int valid = gt_mask[b * NGT + lane];
        int si = lane + (lane >> 4);
        if (valid) {
            s_gtc[si] = make_float4(g.x - g.z * 0.5f, g.y - g.w * 0.5f,
                                    g.x + g.z * 0.5f, g.y + g.w * 0.5f);
            s_areaB[lane] = g.z * g.w;
        } else {
            s_gtc[si] = make_float4(-3e8f, -3e8f, -3e8f, -3e8f);
            s_areaB[lane] = 0.0f;
        }
    }
    __syncwarp();   // warp-local produce -> consume for s_gtc/s_areaB

    // pair mapping: h = lane>>4, loc = w*16 + (lane&15)
    const int loc  = (w << 4) + (lane & 15);
    const int h    = lane >> 4;
    const int n    = nbase + loc;
    const int gloc = b * NLOC + n;
    const unsigned FULL = 0xffffffffu;

    // --- cls-independent work FIRST (overlaps cp.async drain) ---
    float4 t = reinterpret_cast<const float4*>(t_bbox)[gloc];
    float conf_logit = conf[gloc];

    // decode (redundant on both halves — cheaper than broadcasting)
    const int a   = blkmod / 200;                       // block-uniform
    const int rem = (blkmod % 200) * TILE + loc;        // n % 25600
    const int j   = rem / NW;
    const int i   = rem - j * NW;
    float sx = sigmoidf_(t.x), sy = sigmoidf_(t.y);
    float sw = sigmoidf_(t.z), sh = sigmoidf_(t.w);
    float px = (sx * 2.0f - 0.5f + (float)i) * STRIDE_F;
    float py = (sy * 2.0f - 0.5f + (float)j) * STRIDE_F;
    float tw = sw * 2.0f, th = sh * 2.0f;
    float pw = tw * tw * c_anchors[a][0];
    float ph = th * th * c_anchors[a][1];

    float ax1 = px - pw * 0.5f, ax2 = px + pw * 0.5f;
    float ay1 = py - ph * 0.5f, ay2 = py + ph * 0.5f;
    float areaA = (ax2 - ax1) * (ay2 - ay1);

    // IoU vs 16 GTs per half
    float iou = 0.0f;
    #pragma unroll
    for (int k = 0; k < 16; k++) {
        int g = h * 16 + k;
        float4 c = s_gtc[g + (g >> 4)];
        float iw = fmaxf(fminf(ax2, c.z) - fmaxf(ax1, c.x), 0.0f);
        float ih = fmaxf(fminf(ay2, c.w) - fmaxf(ay1, c.y), 0.0f);
        float inter = iw * ih;
        float uni = areaA + s_areaB[g] - inter;
        iou = fmaxf(iou, __fdividef(inter, uni + 1e-16f));
    }
    iou = fmaxf(iou, __shfl_xor_sync(FULL, iou, 16));

    // --- NOW wait for cls tile (mostly already landed) ---
    asm volatile("cp.async.wait_group 0;" ::: "memory");
    __syncwarp();

    // --- P2: class max/argmax (cg = 2k + h, pad-21 conflict-free) ---
    const int base = loc * ROWF4;
    float gm = -1e30f; int gcg = h;
    {
        #pragma unroll
        for (int k = 0; k < 10; k++) {
            int cg = 2 * k + h;
            float4 v = s_cls[base + cg];
            float m = fmaxf(fmaxf(v.x, v.y), fmaxf(v.z, v.w));
            if (m > gm) { gm = m; gcg = cg; }
        }
    }
    float mv = gm; int mi;
    {
        float4 v = s_cls[base + gcg];
        int r = (v.z == gm) ? 2 : 3;
        if (v.y == gm) r = 1;
        if (v.x == gm) r = 0;
        mi = gcg * 4 + r;
    }
    {
        float ov = __shfl_xor_sync(FULL, mv, 16);
        int   oi = __shfl_xor_sync(FULL, mi, 16);
        if (ov > mv || (ov == mv && oi < mi)) { mv = ov; mi = oi; }
    }

    // --- h==0 lanes: streaming outputs + conf bce ---
    float lsum = 0.0f;
    if (h == 0) {
        lsum = bce_(conf_logit, iou);
        __stcs(reinterpret_cast<float4*>(out + OFF_PBBOX) + gloc,
               make_float4(px, py, pw, ph));
        __stcs(out + OFF_CLSIDX + gloc, (float)mi);
        __stcs(out + OFF_SCORE  + gloc, sigmoidf_(conf_logit) * sigmoidf_(mv));
    }

    // --- block 0 additionally: per-GT losses, one GT per thread ---
    if (blockIdx.x == 0) {
        int gb = tid / NGT;
        int gg = tid % NGT;
        if (gt_mask[gb * NGT + gg]) {
            float4 gbx = reinterpret_cast<const float4*>(gt)[gb * NGT + gg];
            float gw = gbx.z, gh = gbx.w;
            int best = 0; float bestr = -1.0f;
            #pragma unroll
            for (int aa = 0; aa < 9; aa++) {
                float aw = c_anchors[aa][0], ah = c_anchors[aa][1];
                float inter = fminf(gw, aw) * fminf(gh, ah);
                float uni = gw * gh + aw * ah - inter;
                float r = inter / (uni + 1e-16f);
                if (r > bestr) { bestr = r; best = aa; }
            }
            if (best < NA) {
                int ta = best;
                float cxs = gbx.x * (1.0f / STRIDE_F);
                float cys = gbx.y * (1.0f / STRIDE_F);
                int ti = min(max((int)cxs, 0), NW - 1);
                int tj = min(max((int)cys, 0), NH - 1);
                int cell = ((gb * NA + ta) * NH + tj) * NW + ti;
                float4 tb = reinterpret_cast<const float4*>(t_bbox)[cell];
                float tgx = (fmodf(cxs, 1.0f) + 0.5f) * 0.5f;
                float tgy = (fmodf(cys, 1.0f) + 0.5f) * 0.5f;
                float tgw = sqrtf(gw / c_anchors[ta][0]) * 0.5f;
                float tgh = sqrtf(gh / c_anchors[ta][1]) * 0.5f;
                lsum += bce_(tb.x, tgx) + bce_(tb.y, tgy);
                lsum += bce_(tb.z, tgw) + bce_(tb.w, tgh);
                const float* cl = cls + cell * NCLS;
                int tc = gt_cls[gb * NGT + gg];
                float lcls = 0.0f;
                #pragma unroll 8
                for (int c = 0; c < NCLS; c++)
                    lcls += bce_(cl[c], (c == tc) ? 1.0f : 0.0f);
                lsum += lcls * (1.0f / NCLS);
            }
        }
    }

    // --- block reduction -> global double accumulator (single barrier) ---
    #pragma unroll
    for (int off = 16; off; off >>= 1)
        lsum += __shfl_down_sync(FULL, lsum, off);
    if (lane == 0) s_warp[w] = lsum;
    __syncthreads();
    if (tid == 0) {
        float s = 0.0f;
        #pragma unroll
        for (int k = 0; k < 8; k++) s += s_warp[k];
        atomicAdd(&g_loss_acc, (double)s);
        __threadfence();
        unsigned int done = atomicAdd(&g_done_count, 1u);
        if (done == NBLK - 1) {
            double total = atomicAdd(&g_loss_acc, 0.0);
            out[OFF_LOSS] = (float)(total * (1.0 / (double)NB));
            g_loss_acc   = 0.0;
            g_done_count = 0u;
        }
    }
}

extern "C" void kernel_launch(void* const* d_in, const int* in_sizes, int n_in,
                              void* d_out, int out_size)
{
    const float* t_bbox = (const float*)d_in[0];
    const float* conf   = (const float*)d_in[1];
    const float* cls    = (const float*)d_in[2];
    const float* gt     = (const float*)d_in[3];
    const int*   gtc    = (const int*)d_in[4];
    const unsigned char* msk = (const unsigned char*)d_in[5];
    float* out = (float*)d_out;

    main_kernel<<<NBLK, 256>>>(t_bbox, conf, cls, gt, gtc, msk, out);
}